// round 8
// baseline (speedup 1.0000x reference)
#include <cuda_runtime.h>
#include <cuda_fp16.h>
#include <math.h>
#include <stdint.h>

#define TT 8192      // tokens = B*S
#define HD 1024      // hidden
#define ID 2752      // intermediate
#define ED 8         // experts
#define KD 2         // top-k

// ---------------- device scratch ----------------
__device__ int    g_cnt[ED];
__device__ int    g_tok[ED][TT];
__device__ int    g_slot[ED][TT];
__device__ float  g_wslot[TT * KD];
__device__ __half g_act[(size_t)TT * KD * ID];   // routed activations fp16 (slot-major)
__device__ __half g_sact[(size_t)TT * ID];       // shared-expert activations fp16
__device__ float  g_outk[(size_t)TT * KD * HD];  // routed outputs (slot-major)
// fp16 converted / transposed operands
__device__ __half g_xh[(size_t)TT * HD];         // x fp16
__device__ __half g_wgt[(size_t)ED * HD * ID];   // Wg^T  [E][I][H]
__device__ __half g_wut[(size_t)ED * HD * ID];   // Wu^T  [E][I][H]
__device__ __half g_wdt[(size_t)ED * ID * HD];   // Wd^T  [E][H][I]
__device__ __half g_sgt[(size_t)HD * ID];        // sg^T  [I][H]
__device__ __half g_sut[(size_t)HD * ID];        // su^T  [I][H]
__device__ __half g_sdt[(size_t)ID * HD];        // sd^T  [H][I]

// ---------------- helpers ----------------
__device__ __forceinline__ uint32_t smem_u32(const void* p) {
    uint32_t a;
    asm("{ .reg .u64 t; cvta.to.shared.u64 t, %1; cvt.u32.u64 %0, t; }" : "=r"(a) : "l"(p));
    return a;
}

#define LDSM_X4(r0, r1, r2, r3, addr) \
    asm volatile("ldmatrix.sync.aligned.m8n8.x4.shared.b16 {%0,%1,%2,%3}, [%4];" \
                 : "=r"(r0), "=r"(r1), "=r"(r2), "=r"(r3) : "r"(addr))

#define MMA16(c, a, b0, b1) \
    asm volatile("mma.sync.aligned.m16n8k16.row.col.f32.f16.f16.f32 " \
                 "{%0,%1,%2,%3}, {%4,%5,%6,%7}, {%8,%9}, {%0,%1,%2,%3};" \
                 : "+f"((c)[0]), "+f"((c)[1]), "+f"((c)[2]), "+f"((c)[3]) \
                 : "r"((a)[0]), "r"((a)[1]), "r"((a)[2]), "r"((a)[3]), "r"(b0), "r"(b1))

#define CP_ASYNC16(dst, src) \
    asm volatile("cp.async.cg.shared.global [%0], [%1], 16;" :: "r"(dst), "l"(src) : "memory")
#define CP_COMMIT() asm volatile("cp.async.commit_group;" ::: "memory")
#define CP_WAIT2()  asm volatile("cp.async.wait_group 2;" ::: "memory")

// 64B-row XOR swizzle: r = row, c = 16B chunk (0..3)
__device__ __forceinline__ uint32_t swz(int r, int c) {
    return (uint32_t)(r * 64 + ((c ^ ((r >> 1) & 3)) << 4));
}

#define STAGE1 24576   // gemm1: A 16KB + Bg 4KB + Bu 4KB
#define STAGE2 24576   // gemm2: A 16KB + B 8KB
#define NSTAGE 4

// ---------------- small kernels ----------------
__global__ void zero_cnt_kernel() {
    if (threadIdx.x < ED) g_cnt[threadIdx.x] = 0;
}

__global__ void gate_kernel(const float* __restrict__ x,
                            const float* __restrict__ gw) {
    int warp = (blockIdx.x * blockDim.x + threadIdx.x) >> 5;
    int lane = threadIdx.x & 31;
    if (warp >= TT) return;
    const float* xr = x + (size_t)warp * HD;

    float acc[ED];
#pragma unroll
    for (int e = 0; e < ED; e++) acc[e] = 0.f;
    for (int h = lane; h < HD; h += 32) {
        float xv = xr[h];
#pragma unroll
        for (int e = 0; e < ED; e++) acc[e] += xv * gw[e * HD + h];
    }
#pragma unroll
    for (int off = 16; off > 0; off >>= 1) {
#pragma unroll
        for (int e = 0; e < ED; e++)
            acc[e] += __shfl_xor_sync(0xFFFFFFFFu, acc[e], off);
    }
    if (lane == 0) {
        float m = acc[0];
#pragma unroll
        for (int e = 1; e < ED; e++) m = fmaxf(m, acc[e]);
        float ex[ED], s = 0.f;
#pragma unroll
        for (int e = 0; e < ED; e++) { ex[e] = expf(acc[e] - m); s += ex[e]; }
        int i0 = 0;
#pragma unroll
        for (int e = 1; e < ED; e++) if (ex[e] > ex[i0]) i0 = e;
        int i1 = -1;
#pragma unroll
        for (int e = 0; e < ED; e++) {
            if (e == i0) continue;
            if (i1 < 0 || ex[e] > ex[i1]) i1 = e;
        }
        float p0 = ex[i0] / s, p1 = ex[i1] / s;
        float d  = p0 + p1 + 1e-20f;
        int t = warp;
        int pos0 = atomicAdd(&g_cnt[i0], 1);
        g_tok[i0][pos0]  = t;
        g_slot[i0][pos0] = 2 * t;
        int pos1 = atomicAdd(&g_cnt[i1], 1);
        g_tok[i1][pos1]  = t;
        g_slot[i1][pos1] = 2 * t + 1;
        g_wslot[2 * t]     = p0 / d;
        g_wslot[2 * t + 1] = p1 / d;
    }
}

// x -> fp16 copy
__global__ void convx_kernel(const float* __restrict__ x) {
    size_t i = ((size_t)blockIdx.x * 256 + threadIdx.x) * 4;
    float4 v = *(const float4*)(x + i);
    *(__half2*)(g_xh + i)     = __floats2half2_rn(v.x, v.y);
    *(__half2*)(g_xh + i + 2) = __floats2half2_rn(v.z, v.w);
}

// transpose+cvt body: src f32 [K][N] -> dst fp16 [N][K], one 32x32 tile per block
__device__ __forceinline__ void tr_tile(const float* __restrict__ src,
                                        __half* __restrict__ dst,
                                        int K, int N, int k0, int n0) {
    __shared__ float tile[32][33];
    int tx = threadIdx.x & 31, ty = threadIdx.x >> 5;  // 256 thr
#pragma unroll
    for (int i = 0; i < 32; i += 8)
        tile[ty + i][tx] = src[(size_t)(k0 + ty + i) * N + n0 + tx];
    __syncthreads();
#pragma unroll
    for (int i = 0; i < 32; i += 8)
        dst[(size_t)(n0 + ty + i) * K + k0 + tx] = __float2half_rn(tile[tx][ty + i]);
}

// merged routed-weight transposes: z<8 wg, z<16 wu, z<24 wd
__global__ void transpose_big(const float* __restrict__ wg, const float* __restrict__ wu,
                              const float* __restrict__ wd,
                              __half* __restrict__ wgt, __half* __restrict__ wut,
                              __half* __restrict__ wdt) {
    int z = blockIdx.z;
    const float* src; __half* dst; int K, N;
    if (z < 8)       { src = wg + (size_t)z * HD * ID;        dst = wgt + (size_t)z * HD * ID;        K = HD; N = ID; }
    else if (z < 16) { src = wu + (size_t)(z - 8) * HD * ID;  dst = wut + (size_t)(z - 8) * HD * ID;  K = HD; N = ID; }
    else             { src = wd + (size_t)(z - 16) * ID * HD; dst = wdt + (size_t)(z - 16) * ID * HD; K = ID; N = HD; }
    int tn = N / 32;
    int n0 = (blockIdx.x % tn) * 32, k0 = (blockIdx.x / tn) * 32;
    tr_tile(src, dst, K, N, k0, n0);
}

// merged shared-weight transposes: z=0 sg, z=1 su, z=2 sd
__global__ void transpose_small(const float* __restrict__ sg, const float* __restrict__ su,
                                const float* __restrict__ sd,
                                __half* __restrict__ sgt, __half* __restrict__ sut,
                                __half* __restrict__ sdt) {
    int z = blockIdx.z;
    const float* src; __half* dst; int K, N;
    if (z == 0)      { src = sg; dst = sgt; K = HD; N = ID; }
    else if (z == 1) { src = su; dst = sut; K = HD; N = ID; }
    else             { src = sd; dst = sdt; K = ID; N = HD; }
    int tn = N / 32;
    int n0 = (blockIdx.x % tn) * 32, k0 = (blockIdx.x / tn) * 32;
    tr_tile(src, dst, K, N, k0, n0);
}

// ---------------- GEMM 1: act = silu(X@Wg) * (X@Wu)  [fp16 MMA] ----------------
// BM=256, BN=64 i-cols, BK=32. 512 threads = 16 warps (4M x 4N); warp tile 64x16/matrix.
__global__ __launch_bounds__(512, 1)
void gemm1_mma(const __half* __restrict__ Xh,
               const __half* __restrict__ Wgt_base,
               const __half* __restrict__ Wut_base,
               const __half* __restrict__ Sgt,
               const __half* __restrict__ Sut,
               __half* __restrict__ ActR,
               __half* __restrict__ ActS) {
    int e = blockIdx.z;
    int n; const __half *Wg, *Wu; __half* Act; int routed = (e < ED);
    if (routed) { n = g_cnt[e]; Wg = Wgt_base + (size_t)e * HD * ID; Wu = Wut_base + (size_t)e * HD * ID; Act = ActR; }
    else        { n = TT;       Wg = Sgt;                             Wu = Sut;                             Act = ActS; }
    int row0 = blockIdx.y * 256;
    if (row0 >= n) return;
    int col0 = blockIdx.x * 64;

    extern __shared__ __align__(16) char dyn[];
    uint32_t smem = smem_u32(dyn);
    __shared__ int s_tok[256], s_orow[256];

    int tid = threadIdx.x;
    if (tid < 256) {
        int r = row0 + tid;
        int t, o;
        if (routed) { t = (r < n) ? g_tok[e][r] : g_tok[e][0];
                      o = (r < n) ? g_slot[e][r] : 0; }
        else        { t = (r < n) ? r : 0; o = t; }
        s_tok[tid] = t; s_orow[tid] = o;
    }
    __syncthreads();

    int w = tid >> 5, lane = tid & 31;
    int wm = (w >> 2) * 64, wn = (w & 3) * 16;
    int gi = lane >> 2, tig = lane & 3;
    int l15 = lane & 15, l16 = lane >> 4;

    float cg[4][2][4], cu[4][2][4];
#pragma unroll
    for (int mt = 0; mt < 4; mt++)
#pragma unroll
        for (int nt = 0; nt < 2; nt++)
#pragma unroll
            for (int i = 0; i < 4; i++) { cg[mt][nt][i] = 0.f; cu[mt][nt][i] = 0.f; }

    auto issue = [&](int c) {
        uint32_t base = smem + (c & (NSTAGE - 1)) * STAGE1;
        uint32_t As = base, Bg_s = base + 16384, Bu_s = base + 20480;
        int k0 = c * 32;
        // A: 256 rows x 4 chunks = 1024 loads / 512 thr
#pragma unroll
        for (int it = 0; it < 2; it++) {
            int i = tid + it * 512; int r = i >> 2, q = i & 3;
            CP_ASYNC16(As + swz(r, q), Xh + (size_t)s_tok[r] * HD + k0 + q * 8);
        }
        // Bg (tid<256) / Bu (tid>=256): 64 rows x 4 chunks each
        {
            int i = tid & 255; int r = i >> 2, q = i & 3;
            uint32_t d = swz(r, q);
            const __half* src = (tid < 256) ? (Wg + (size_t)(col0 + r) * HD + k0 + q * 8)
                                            : (Wu + (size_t)(col0 + r) * HD + k0 + q * 8);
            uint32_t dst = ((tid < 256) ? Bg_s : Bu_s) + d;
            CP_ASYNC16(dst, src);
        }
    };
    auto compute = [&](uint32_t base) {
        uint32_t As = base, Bg_s = base + 16384, Bu_s = base + 20480;
#pragma unroll
        for (int s = 0; s < 2; s++) {
            int c = s * 2 + l16;
            uint32_t a[4][4], bg[4], bu[4];
#pragma unroll
            for (int mt = 0; mt < 4; mt++) {
                int row = wm + mt * 16 + l15;
                LDSM_X4(a[mt][0], a[mt][1], a[mt][2], a[mt][3], As + swz(row, c));
            }
            {
                int row = wn + l15;
                uint32_t off = swz(row, c);
                LDSM_X4(bg[0], bg[1], bg[2], bg[3], Bg_s + off);
                LDSM_X4(bu[0], bu[1], bu[2], bu[3], Bu_s + off);
            }
#pragma unroll
            for (int mt = 0; mt < 4; mt++) {
                MMA16(cg[mt][0], a[mt], bg[0], bg[2]);
                MMA16(cg[mt][1], a[mt], bg[1], bg[3]);
                MMA16(cu[mt][0], a[mt], bu[0], bu[2]);
                MMA16(cu[mt][1], a[mt], bu[1], bu[3]);
            }
        }
    };

    const int NCH = HD / 32;  // 32
    issue(0); CP_COMMIT();
    issue(1); CP_COMMIT();
    issue(2); CP_COMMIT();
    for (int c = 0; c < NCH; c++) {
        CP_WAIT2();
        __syncthreads();
        if (c + 3 < NCH) issue(c + 3);
        CP_COMMIT();
        compute(smem + (c & (NSTAGE - 1)) * STAGE1);
    }

    // epilogue: silu(g)*u, fp16 stores to gathered rows
#pragma unroll
    for (int mt = 0; mt < 4; mt++)
#pragma unroll
        for (int nt = 0; nt < 2; nt++) {
            int col = col0 + wn + nt * 8 + tig * 2;
#pragma unroll
            for (int h = 0; h < 2; h++) {
                int lr = wm + mt * 16 + gi + h * 8;
                if (row0 + lr < n) {
                    float g0 = cg[mt][nt][h * 2], g1 = cg[mt][nt][h * 2 + 1];
                    float u0 = cu[mt][nt][h * 2], u1 = cu[mt][nt][h * 2 + 1];
                    float o0 = g0 / (1.f + expf(-g0)) * u0;
                    float o1 = g1 / (1.f + expf(-g1)) * u1;
                    *(__half2*)(Act + (size_t)s_orow[lr] * ID + col) =
                        __floats2half2_rn(o0, o1);
                }
            }
        }
}

// ---------------- GEMM 2: Out = Act @ Wd  [fp16 MMA] ----------------
// BM=256, BN=128, BK=32. 512 threads = 16 warps (4M x 4N); warp tile 64x32.
__global__ __launch_bounds__(512, 1)
void gemm2_mma(const __half* __restrict__ ActR,
               const __half* __restrict__ ActS,
               const __half* __restrict__ Wdt_base,
               const __half* __restrict__ Sdt,
               float* __restrict__ OutR,
               float* __restrict__ OutS) {
    int e = blockIdx.z;
    int n; const __half *Wd, *Src; float* Out; int routed = (e < ED);
    if (routed) { n = g_cnt[e]; Wd = Wdt_base + (size_t)e * ID * HD; Src = ActR; Out = OutR; }
    else        { n = TT;       Wd = Sdt;                             Src = ActS; Out = OutS; }
    int row0 = blockIdx.y * 256;
    if (row0 >= n) return;
    int col0 = blockIdx.x * 128;

    extern __shared__ __align__(16) char dyn[];
    uint32_t smem = smem_u32(dyn);
    __shared__ int s_row[256];

    int tid = threadIdx.x;
    if (tid < 256) {
        int r = row0 + tid;
        int a;
        if (routed) a = (r < n) ? g_slot[e][r] : 0;
        else        a = (r < n) ? r : 0;
        s_row[tid] = a;
    }
    __syncthreads();

    int w = tid >> 5, lane = tid & 31;
    int wm = (w >> 2) * 64, wn = (w & 3) * 32;
    int gi = lane >> 2, tig = lane & 3;
    int l15 = lane & 15, l16 = lane >> 4;

    float cc[4][4][4];
#pragma unroll
    for (int mt = 0; mt < 4; mt++)
#pragma unroll
        for (int nt = 0; nt < 4; nt++)
#pragma unroll
            for (int i = 0; i < 4; i++) cc[mt][nt][i] = 0.f;

    auto issue = [&](int c) {
        uint32_t base = smem + (c & (NSTAGE - 1)) * STAGE2;
        uint32_t As = base, Bs = base + 16384;
        int k0 = c * 32;
#pragma unroll
        for (int it = 0; it < 2; it++) {
            int i = tid + it * 512; int r = i >> 2, q = i & 3;
            CP_ASYNC16(As + swz(r, q), Src + (size_t)s_row[r] * ID + k0 + q * 8);
        }
        {
            int r = tid >> 2, q = tid & 3;   // 128 rows x 4 chunks = 512 loads
            CP_ASYNC16(Bs + swz(r, q), Wd + (size_t)(col0 + r) * ID + k0 + q * 8);
        }
    };
    auto compute = [&](uint32_t base) {
        uint32_t As = base, Bs = base + 16384;
#pragma unroll
        for (int s = 0; s < 2; s++) {
            int c = s * 2 + l16;
            uint32_t a[4][4], b[2][4];
#pragma unroll
            for (int mt = 0; mt < 4; mt++) {
                int row = wm + mt * 16 + l15;
                LDSM_X4(a[mt][0], a[mt][1], a[mt][2], a[mt][3], As + swz(row, c));
            }
#pragma unroll
            for (int p = 0; p < 2; p++) {
                int row = wn + p * 16 + l15;
                LDSM_X4(b[p][0], b[p][1], b[p][2], b[p][3], Bs + swz(row, c));
            }
#pragma unroll
            for (int mt = 0; mt < 4; mt++)
#pragma unroll
                for (int p = 0; p < 2; p++) {
                    MMA16(cc[mt][2 * p],     a[mt], b[p][0], b[p][2]);
                    MMA16(cc[mt][2 * p + 1], a[mt], b[p][1], b[p][3]);
                }
        }
    };

    const int NCH = ID / 32;  // 86
    issue(0); CP_COMMIT();
    issue(1); CP_COMMIT();
    issue(2); CP_COMMIT();
    for (int c = 0; c < NCH; c++) {
        CP_WAIT2();
        __syncthreads();
        if (c + 3 < NCH) issue(c + 3);
        CP_COMMIT();
        compute(smem + (c & (NSTAGE - 1)) * STAGE2);
    }

#pragma unroll
    for (int mt = 0; mt < 4; mt++)
#pragma unroll
        for (int nt = 0; nt < 4; nt++) {
            int col = col0 + wn + nt * 8 + tig * 2;
#pragma unroll
            for (int h = 0; h < 2; h++) {
                int lr = wm + mt * 16 + gi + h * 8;
                if (row0 + lr < n) {
                    float2 o;
                    o.x = cc[mt][nt][h * 2];
                    o.y = cc[mt][nt][h * 2 + 1];
                    *(float2*)(Out + (size_t)s_row[lr] * HD + col) = o;
                }
            }
        }
}

// out[t] += w0*outk[2t] + w1*outk[2t+1]
__global__ void combine_kernel(float* __restrict__ out) {
    int t = blockIdx.x;
    int h = threadIdx.x;
    float w0 = g_wslot[2 * t];
    float w1 = g_wslot[2 * t + 1];
    size_t base = (size_t)(2 * t) * HD + h;
    float v = out[(size_t)t * HD + h];
    v += w0 * g_outk[base] + w1 * g_outk[base + HD];
    out[(size_t)t * HD + h] = v;
}

// ---------------- launch ----------------
extern "C" void kernel_launch(void* const* d_in, const int* in_sizes, int n_in,
                              void* d_out, int out_size) {
    const float* x  = (const float*)d_in[0];
    const float* gw = (const float*)d_in[1];
    const float* wg = (const float*)d_in[2];
    const float* wu = (const float*)d_in[3];
    const float* wd = (const float*)d_in[4];
    const float* sg = (const float*)d_in[5];
    const float* su = (const float*)d_in[6];
    const float* sd = (const float*)d_in[7];
    float* out = (float*)d_out;

    const int SMEM1 = NSTAGE * STAGE1;  // 96KB
    const int SMEM2 = NSTAGE * STAGE2;  // 96KB
    cudaFuncSetAttribute(gemm1_mma, cudaFuncAttributeMaxDynamicSharedMemorySize, SMEM1);
    cudaFuncSetAttribute(gemm2_mma, cudaFuncAttributeMaxDynamicSharedMemorySize, SMEM2);

    __half* xh;  cudaGetSymbolAddress((void**)&xh,  g_xh);
    __half* wgt; cudaGetSymbolAddress((void**)&wgt, g_wgt);
    __half* wut; cudaGetSymbolAddress((void**)&wut, g_wut);
    __half* wdt; cudaGetSymbolAddress((void**)&wdt, g_wdt);
    __half* sgt; cudaGetSymbolAddress((void**)&sgt, g_sgt);
    __half* sut; cudaGetSymbolAddress((void**)&sut, g_sut);
    __half* sdt; cudaGetSymbolAddress((void**)&sdt, g_sdt);
    __half* act; cudaGetSymbolAddress((void**)&act, g_act);
    __half* sact;cudaGetSymbolAddress((void**)&sact,g_sact);
    float* outk; cudaGetSymbolAddress((void**)&outk,g_outk);

    transpose_big<<<dim3(2752, 1, 24), 256>>>(wg, wu, wd, wgt, wut, wdt);
    transpose_small<<<dim3(2752, 1, 3), 256>>>(sg, su, sd, sgt, sut, sdt);
    zero_cnt_kernel<<<1, 32>>>();
    gate_kernel<<<TT / 8, 256>>>(x, gw);
    convx_kernel<<<TT * HD / 1024, 256>>>(x);

    {
        dim3 g1(ID / 64, TT / 256, ED + 1);     // (43, 32, 9)
        gemm1_mma<<<g1, 512, SMEM1>>>(xh, wgt, wut, sgt, sut, act, sact);
        dim3 g2(HD / 128, TT / 256, ED + 1);    // (8, 32, 9)
        gemm2_mma<<<g2, 512, SMEM2>>>(act, sact, wdt, sdt, outk, out);
    }
    combine_kernel<<<TT, HD>>>(out);
}

// round 9
// speedup vs baseline: 1.1619x; 1.1619x over previous
#include <cuda_runtime.h>
#include <cuda_fp16.h>
#include <math.h>
#include <stdint.h>

#define TT 8192      // tokens = B*S
#define HD 1024      // hidden
#define ID 2752      // intermediate
#define ED 8         // experts
#define KD 2         // top-k

// ---------------- device scratch ----------------
__device__ int    g_cnt[ED];
__device__ int    g_tok[ED][TT];
__device__ int    g_slot[ED][TT];
__device__ float  g_wslot[TT * KD];
__device__ __half g_act[(size_t)TT * KD * ID];
__device__ __half g_sact[(size_t)TT * ID];
__device__ float  g_outk[(size_t)TT * KD * HD];
__device__ __half g_xh[(size_t)TT * HD];
__device__ __half g_wgt[(size_t)ED * HD * ID];   // Wg^T [E][I][H]
__device__ __half g_wut[(size_t)ED * HD * ID];   // Wu^T [E][I][H]
__device__ __half g_wdt[(size_t)ED * ID * HD];   // Wd^T [E][H][I]
__device__ __half g_sgt[(size_t)HD * ID];
__device__ __half g_sut[(size_t)HD * ID];
__device__ __half g_sdt[(size_t)ID * HD];

// ---------------- helpers ----------------
__device__ __forceinline__ uint32_t smem_u32(const void* p) {
    uint32_t a;
    asm("{ .reg .u64 t; cvta.to.shared.u64 t, %1; cvt.u32.u64 %0, t; }" : "=r"(a) : "l"(p));
    return a;
}

#define LDSM_X4(r0, r1, r2, r3, addr) \
    asm volatile("ldmatrix.sync.aligned.m8n8.x4.shared.b16 {%0,%1,%2,%3}, [%4];" \
                 : "=r"(r0), "=r"(r1), "=r"(r2), "=r"(r3) : "r"(addr))

#define MMA16(c, a, b0, b1) \
    asm volatile("mma.sync.aligned.m16n8k16.row.col.f32.f16.f16.f32 " \
                 "{%0,%1,%2,%3}, {%4,%5,%6,%7}, {%8,%9}, {%0,%1,%2,%3};" \
                 : "+f"((c)[0]), "+f"((c)[1]), "+f"((c)[2]), "+f"((c)[3]) \
                 : "r"((a)[0]), "r"((a)[1]), "r"((a)[2]), "r"((a)[3]), "r"(b0), "r"(b1))

#define CP_ASYNC16(dst, src) \
    asm volatile("cp.async.cg.shared.global [%0], [%1], 16;" :: "r"(dst), "l"(src) : "memory")
#define CP_COMMIT() asm volatile("cp.async.commit_group;" ::: "memory")
#define CP_WAIT1()  asm volatile("cp.async.wait_group 1;" ::: "memory")

// 128B-row XOR swizzle: r = row, c = 16B chunk (0..7)
__device__ __forceinline__ uint32_t swz(int r, int c) {
    return (uint32_t)(r * 128 + ((c ^ (r & 7)) << 4));
}

#define STAGE1 32768   // gemm1: A 16KB + Bg 8KB + Bu 8KB   (BK=64)
#define STAGE2 49152   // gemm2: A 32KB + B 16KB            (BK=64)

// ---------------- gate + x->fp16 fused ----------------
__global__ void gatecvt_kernel(const float* __restrict__ x,
                               const float* __restrict__ gw) {
    int warp = (blockIdx.x * blockDim.x + threadIdx.x) >> 5;
    int lane = threadIdx.x & 31;
    if (warp >= TT) return;
    const float* xr = x + (size_t)warp * HD;
    __half* xo = g_xh + (size_t)warp * HD;

    float acc[ED];
#pragma unroll
    for (int e = 0; e < ED; e++) acc[e] = 0.f;
    for (int h = lane * 2; h < HD; h += 64) {
        float2 v = *(const float2*)(xr + h);
        *(__half2*)(xo + h) = __floats2half2_rn(v.x, v.y);
#pragma unroll
        for (int e = 0; e < ED; e++)
            acc[e] += v.x * gw[e * HD + h] + v.y * gw[e * HD + h + 1];
    }
#pragma unroll
    for (int off = 16; off > 0; off >>= 1) {
#pragma unroll
        for (int e = 0; e < ED; e++)
            acc[e] += __shfl_xor_sync(0xFFFFFFFFu, acc[e], off);
    }
    if (lane == 0) {
        float m = acc[0];
#pragma unroll
        for (int e = 1; e < ED; e++) m = fmaxf(m, acc[e]);
        float ex[ED], s = 0.f;
#pragma unroll
        for (int e = 0; e < ED; e++) { ex[e] = expf(acc[e] - m); s += ex[e]; }
        int i0 = 0;
#pragma unroll
        for (int e = 1; e < ED; e++) if (ex[e] > ex[i0]) i0 = e;
        int i1 = -1;
#pragma unroll
        for (int e = 0; e < ED; e++) {
            if (e == i0) continue;
            if (i1 < 0 || ex[e] > ex[i1]) i1 = e;
        }
        float p0 = ex[i0] / s, p1 = ex[i1] / s;
        float d  = p0 + p1 + 1e-20f;
        int t = warp;
        int pos0 = atomicAdd(&g_cnt[i0], 1);
        g_tok[i0][pos0]  = t;
        g_slot[i0][pos0] = 2 * t;
        int pos1 = atomicAdd(&g_cnt[i1], 1);
        g_tok[i1][pos1]  = t;
        g_slot[i1][pos1] = 2 * t + 1;
        g_wslot[2 * t]     = p0 / d;
        g_wslot[2 * t + 1] = p1 / d;
    }
}

// transpose+cvt body: src f32 [K][N] -> dst fp16 [N][K]
__device__ __forceinline__ void tr_tile(const float* __restrict__ src,
                                        __half* __restrict__ dst,
                                        int K, int N, int k0, int n0) {
    __shared__ float tile[32][33];
    int tx = threadIdx.x & 31, ty = threadIdx.x >> 5;
#pragma unroll
    for (int i = 0; i < 32; i += 8)
        tile[ty + i][tx] = src[(size_t)(k0 + ty + i) * N + n0 + tx];
    __syncthreads();
#pragma unroll
    for (int i = 0; i < 32; i += 8)
        dst[(size_t)(n0 + ty + i) * K + k0 + tx] = __float2half_rn(tile[tx][ty + i]);
}

__global__ void transpose_big(const float* __restrict__ wg, const float* __restrict__ wu,
                              const float* __restrict__ wd,
                              __half* __restrict__ wgt, __half* __restrict__ wut,
                              __half* __restrict__ wdt) {
    int z = blockIdx.z;
    const float* src; __half* dst; int K, N;
    if (z < 8)       { src = wg + (size_t)z * HD * ID;        dst = wgt + (size_t)z * HD * ID;        K = HD; N = ID; }
    else if (z < 16) { src = wu + (size_t)(z - 8) * HD * ID;  dst = wut + (size_t)(z - 8) * HD * ID;  K = HD; N = ID; }
    else             { src = wd + (size_t)(z - 16) * ID * HD; dst = wdt + (size_t)(z - 16) * ID * HD; K = ID; N = HD; }
    int tn = N / 32;
    int n0 = (blockIdx.x % tn) * 32, k0 = (blockIdx.x / tn) * 32;
    tr_tile(src, dst, K, N, k0, n0);
}

// also zeroes g_cnt (runs before gatecvt)
__global__ void transpose_small(const float* __restrict__ sg, const float* __restrict__ su,
                                const float* __restrict__ sd,
                                __half* __restrict__ sgt, __half* __restrict__ sut,
                                __half* __restrict__ sdt) {
    if (blockIdx.x == 0 && blockIdx.z == 0 && threadIdx.x < ED) g_cnt[threadIdx.x] = 0;
    int z = blockIdx.z;
    const float* src; __half* dst; int K, N;
    if (z == 0)      { src = sg; dst = sgt; K = HD; N = ID; }
    else if (z == 1) { src = su; dst = sut; K = HD; N = ID; }
    else             { src = sd; dst = sdt; K = ID; N = HD; }
    int tn = N / 32;
    int n0 = (blockIdx.x % tn) * 32, k0 = (blockIdx.x / tn) * 32;
    tr_tile(src, dst, K, N, k0, n0);
}

// ---------------- GEMM 1: act = silu(X@Wg)*(X@Wu)  BM=128 BN=64 BK=64, 8 warps, occ 2 ----------------
__global__ __launch_bounds__(256, 2)
void gemm1_mma(const __half* __restrict__ Xh,
               const __half* __restrict__ Wgt_base,
               const __half* __restrict__ Wut_base,
               const __half* __restrict__ Sgt,
               const __half* __restrict__ Sut,
               __half* __restrict__ ActR,
               __half* __restrict__ ActS) {
    int e = blockIdx.z;
    int n; const __half *Wg, *Wu; __half* Act; int routed = (e < ED);
    if (routed) { n = g_cnt[e]; Wg = Wgt_base + (size_t)e * HD * ID; Wu = Wut_base + (size_t)e * HD * ID; Act = ActR; }
    else        { n = TT;       Wg = Sgt;                             Wu = Sut;                             Act = ActS; }
    int row0 = blockIdx.y * 128;
    if (row0 >= n) return;
    int col0 = blockIdx.x * 64;

    extern __shared__ __align__(16) char dyn[];
    uint32_t smem = smem_u32(dyn);
    __shared__ int s_tok[128], s_orow[128];

    int tid = threadIdx.x;
    if (tid < 128) {
        int r = row0 + tid;
        int t, o;
        if (routed) { t = (r < n) ? g_tok[e][r] : g_tok[e][0];
                      o = (r < n) ? g_slot[e][r] : 0; }
        else        { t = (r < n) ? r : 0; o = t; }
        s_tok[tid] = t; s_orow[tid] = o;
    }
    __syncthreads();

    int w = tid >> 5, lane = tid & 31;
    int wm = (w >> 2) * 64, wn = (w & 3) * 16;
    int gi = lane >> 2, tig = lane & 3;
    int l15 = lane & 15, l16 = lane >> 4;

    float cg[4][2][4], cu[4][2][4];
#pragma unroll
    for (int mt = 0; mt < 4; mt++)
#pragma unroll
        for (int nt = 0; nt < 2; nt++)
#pragma unroll
            for (int i = 0; i < 4; i++) { cg[mt][nt][i] = 0.f; cu[mt][nt][i] = 0.f; }

    auto issue = [&](int c, int buf) {
        uint32_t base = smem + buf * STAGE1;
        uint32_t As = base, Bg_s = base + 16384, Bu_s = base + 24576;
        int k0 = c * 64;
        // A: 128 rows x 8 chunks = 1024 / 256 thr
#pragma unroll
        for (int it = 0; it < 4; it++) {
            int i = tid + it * 256; int r = i >> 3, q = i & 7;
            CP_ASYNC16(As + swz(r, q), Xh + (size_t)s_tok[r] * HD + k0 + q * 8);
        }
        // Bg/Bu: 64 rows x 8 chunks each
#pragma unroll
        for (int it = 0; it < 2; it++) {
            int i = tid + it * 256; int r = i >> 3, q = i & 7;
            uint32_t d = swz(r, q);
            CP_ASYNC16(Bg_s + d, Wg + (size_t)(col0 + r) * HD + k0 + q * 8);
            CP_ASYNC16(Bu_s + d, Wu + (size_t)(col0 + r) * HD + k0 + q * 8);
        }
    };
    auto compute = [&](int buf) {
        uint32_t base = smem + buf * STAGE1;
        uint32_t As = base, Bg_s = base + 16384, Bu_s = base + 24576;
#pragma unroll
        for (int s = 0; s < 4; s++) {
            int c = s * 2 + l16;
            uint32_t a[4][4], bg[4], bu[4];
#pragma unroll
            for (int mt = 0; mt < 4; mt++) {
                int row = wm + mt * 16 + l15;
                LDSM_X4(a[mt][0], a[mt][1], a[mt][2], a[mt][3], As + swz(row, c));
            }
            {
                int row = wn + l15;
                uint32_t off = swz(row, c);
                LDSM_X4(bg[0], bg[1], bg[2], bg[3], Bg_s + off);
                LDSM_X4(bu[0], bu[1], bu[2], bu[3], Bu_s + off);
            }
#pragma unroll
            for (int mt = 0; mt < 4; mt++) {
                MMA16(cg[mt][0], a[mt], bg[0], bg[2]);
                MMA16(cg[mt][1], a[mt], bg[1], bg[3]);
                MMA16(cu[mt][0], a[mt], bu[0], bu[2]);
                MMA16(cu[mt][1], a[mt], bu[1], bu[3]);
            }
        }
    };

    const int NCH = HD / 64;  // 16
    issue(0, 0); CP_COMMIT();
    issue(1, 1); CP_COMMIT();
    int buf = 0;
    for (int c = 0; c < NCH; c++) {
        CP_WAIT1();
        __syncthreads();
        if (c + 2 < NCH) {
            int b2 = buf + 2; if (b2 >= 3) b2 -= 3;
            issue(c + 2, b2);
        }
        CP_COMMIT();
        compute(buf);
        if (++buf == 3) buf = 0;
    }

#pragma unroll
    for (int mt = 0; mt < 4; mt++)
#pragma unroll
        for (int nt = 0; nt < 2; nt++) {
            int col = col0 + wn + nt * 8 + tig * 2;
#pragma unroll
            for (int h = 0; h < 2; h++) {
                int lr = wm + mt * 16 + gi + h * 8;
                if (row0 + lr < n) {
                    float g0 = cg[mt][nt][h * 2], g1 = cg[mt][nt][h * 2 + 1];
                    float u0 = cu[mt][nt][h * 2], u1 = cu[mt][nt][h * 2 + 1];
                    float o0 = g0 / (1.f + expf(-g0)) * u0;
                    float o1 = g1 / (1.f + expf(-g1)) * u1;
                    *(__half2*)(Act + (size_t)s_orow[lr] * ID + col) =
                        __floats2half2_rn(o0, o1);
                }
            }
        }
}

// ---------------- GEMM 2: Out = Act @ Wd  BM=256 BN=128 BK=64, 8 warps (4Mx2N, 64x64) ----------------
__global__ __launch_bounds__(256, 1)
void gemm2_mma(const __half* __restrict__ ActR,
               const __half* __restrict__ ActS,
               const __half* __restrict__ Wdt_base,
               const __half* __restrict__ Sdt,
               float* __restrict__ OutR,
               float* __restrict__ OutS) {
    int e = blockIdx.z;
    int n; const __half *Wd, *Src; float* Out; int routed = (e < ED);
    if (routed) { n = g_cnt[e]; Wd = Wdt_base + (size_t)e * ID * HD; Src = ActR; Out = OutR; }
    else        { n = TT;       Wd = Sdt;                             Src = ActS; Out = OutS; }
    int row0 = blockIdx.y * 256;
    if (row0 >= n) return;
    int col0 = blockIdx.x * 128;

    extern __shared__ __align__(16) char dyn[];
    uint32_t smem = smem_u32(dyn);
    __shared__ int s_row[256];

    int tid = threadIdx.x;
    {
        int r = row0 + tid;
        int a;
        if (routed) a = (r < n) ? g_slot[e][r] : 0;
        else        a = (r < n) ? r : 0;
        s_row[tid] = a;
    }
    __syncthreads();

    int w = tid >> 5, lane = tid & 31;
    int wm = (w >> 1) * 64, wn = (w & 1) * 64;
    int gi = lane >> 2, tig = lane & 3;
    int l15 = lane & 15, l16 = lane >> 4;

    float cc[4][8][4];
#pragma unroll
    for (int mt = 0; mt < 4; mt++)
#pragma unroll
        for (int nt = 0; nt < 8; nt++)
#pragma unroll
            for (int i = 0; i < 4; i++) cc[mt][nt][i] = 0.f;

    auto issue = [&](int c, int buf) {
        uint32_t base = smem + buf * STAGE2;
        uint32_t As = base, Bs = base + 32768;
        int k0 = c * 64;
        // A: 256 rows x 8 chunks = 2048 / 256 thr
#pragma unroll
        for (int it = 0; it < 8; it++) {
            int i = tid + it * 256; int r = i >> 3, q = i & 7;
            CP_ASYNC16(As + swz(r, q), Src + (size_t)s_row[r] * ID + k0 + q * 8);
        }
        // B: 128 rows x 8 chunks = 1024
#pragma unroll
        for (int it = 0; it < 4; it++) {
            int i = tid + it * 256; int r = i >> 3, q = i & 7;
            CP_ASYNC16(Bs + swz(r, q), Wd + (size_t)(col0 + r) * ID + k0 + q * 8);
        }
    };
    auto compute = [&](int buf) {
        uint32_t base = smem + buf * STAGE2;
        uint32_t As = base, Bs = base + 32768;
#pragma unroll
        for (int s = 0; s < 4; s++) {
            int c = s * 2 + l16;
            uint32_t a[4][4], b[4][4];
#pragma unroll
            for (int mt = 0; mt < 4; mt++) {
                int row = wm + mt * 16 + l15;
                LDSM_X4(a[mt][0], a[mt][1], a[mt][2], a[mt][3], As + swz(row, c));
            }
#pragma unroll
            for (int p = 0; p < 4; p++) {
                int row = wn + p * 16 + l15;
                LDSM_X4(b[p][0], b[p][1], b[p][2], b[p][3], Bs + swz(row, c));
            }
#pragma unroll
            for (int mt = 0; mt < 4; mt++)
#pragma unroll
                for (int p = 0; p < 4; p++) {
                    MMA16(cc[mt][2 * p],     a[mt], b[p][0], b[p][2]);
                    MMA16(cc[mt][2 * p + 1], a[mt], b[p][1], b[p][3]);
                }
        }
    };

    const int NCH = ID / 64;  // 43
    issue(0, 0); CP_COMMIT();
    issue(1, 1); CP_COMMIT();
    int buf = 0;
    for (int c = 0; c < NCH; c++) {
        CP_WAIT1();
        __syncthreads();
        if (c + 2 < NCH) {
            int b2 = buf + 2; if (b2 >= 3) b2 -= 3;
            issue(c + 2, b2);
        }
        CP_COMMIT();
        compute(buf);
        if (++buf == 3) buf = 0;
    }

#pragma unroll
    for (int mt = 0; mt < 4; mt++)
#pragma unroll
        for (int nt = 0; nt < 8; nt++) {
            int col = col0 + wn + nt * 8 + tig * 2;
#pragma unroll
            for (int h = 0; h < 2; h++) {
                int lr = wm + mt * 16 + gi + h * 8;
                if (row0 + lr < n) {
                    float2 o;
                    o.x = cc[mt][nt][h * 2];
                    o.y = cc[mt][nt][h * 2 + 1];
                    *(float2*)(Out + (size_t)s_row[lr] * HD + col) = o;
                }
            }
        }
}

// out[t] += w0*outk[2t] + w1*outk[2t+1]
__global__ void combine_kernel(float* __restrict__ out) {
    int t = blockIdx.x;
    int h = threadIdx.x;
    float w0 = g_wslot[2 * t];
    float w1 = g_wslot[2 * t + 1];
    size_t base = (size_t)(2 * t) * HD + h;
    float v = out[(size_t)t * HD + h];
    v += w0 * g_outk[base] + w1 * g_outk[base + HD];
    out[(size_t)t * HD + h] = v;
}

// ---------------- launch ----------------
extern "C" void kernel_launch(void* const* d_in, const int* in_sizes, int n_in,
                              void* d_out, int out_size) {
    const float* x  = (const float*)d_in[0];
    const float* gw = (const float*)d_in[1];
    const float* wg = (const float*)d_in[2];
    const float* wu = (const float*)d_in[3];
    const float* wd = (const float*)d_in[4];
    const float* sg = (const float*)d_in[5];
    const float* su = (const float*)d_in[6];
    const float* sd = (const float*)d_in[7];
    float* out = (float*)d_out;

    const int SMEM1 = 3 * STAGE1;  // 96KB, occ 2
    const int SMEM2 = 3 * STAGE2;  // 144KB, occ 1
    cudaFuncSetAttribute(gemm1_mma, cudaFuncAttributeMaxDynamicSharedMemorySize, SMEM1);
    cudaFuncSetAttribute(gemm2_mma, cudaFuncAttributeMaxDynamicSharedMemorySize, SMEM2);

    __half* xh;  cudaGetSymbolAddress((void**)&xh,  g_xh);
    __half* wgt; cudaGetSymbolAddress((void**)&wgt, g_wgt);
    __half* wut; cudaGetSymbolAddress((void**)&wut, g_wut);
    __half* wdt; cudaGetSymbolAddress((void**)&wdt, g_wdt);
    __half* sgt; cudaGetSymbolAddress((void**)&sgt, g_sgt);
    __half* sut; cudaGetSymbolAddress((void**)&sut, g_sut);
    __half* sdt; cudaGetSymbolAddress((void**)&sdt, g_sdt);
    __half* act; cudaGetSymbolAddress((void**)&act, g_act);
    __half* sact;cudaGetSymbolAddress((void**)&sact,g_sact);
    float* outk; cudaGetSymbolAddress((void**)&outk,g_outk);

    transpose_big<<<dim3(2752, 1, 24), 256>>>(wg, wu, wd, wgt, wut, wdt);     // 1
    transpose_small<<<dim3(2752, 1, 3), 256>>>(sg, su, sd, sgt, sut, sdt);    // 2 (zeroes g_cnt)
    gatecvt_kernel<<<TT / 8, 256>>>(x, gw);                                   // 3

    dim3 g1(ID / 64, TT / 128, ED + 1);     // (43, 64, 9)
    gemm1_mma<<<g1, 256, SMEM1>>>(xh, wgt, wut, sgt, sut, act, sact);         // 4 <- profiled
    dim3 g2(HD / 128, TT / 256, ED + 1);    // (8, 32, 9)
    gemm2_mma<<<g2, 256, SMEM2>>>(act, sact, wdt, sdt, outk, out);            // 5
    combine_kernel<<<TT, HD>>>(out);                                          // 6
}